// round 4
// baseline (speedup 1.0000x reference)
#include <cuda_runtime.h>

#define NBINS   256
#define TPB     384                      // 12 warps
#define KQ      5                        // quads held in registers per thread
#define NGROUPS (TPB / 128)              // 3 warpgroups of 4 warps per 128B row
#define HIST_BYTES (2 * NBINS * NGROUPS * 128)   // 192 KB lane-private u8 counters

__device__ int   g_hist[2 * NBINS];      // zero-init; restored to zero each run
__device__ float g_pxmap[NBINS];
__device__ int   g_done0;
__device__ int   g_done1;
__device__ volatile int g_release;

extern __shared__ unsigned char s_dyn[]; // dynamic: u8 histogram counters

// lane-private u8 counter increment. Within a warp (fixed h,bin,row,byte) the
// 32 lanes hit 32 distinct banks -> conflict-free LDS.U8/STS.U8 RMW, no atomics.
__device__ __forceinline__ void hinc(unsigned char* hp, int h, int bin,
                                     int wrow, int wbyte, int lane) {
    unsigned char* p = hp + ((((h * NBINS + bin) * NGROUPS) + wrow) << 7)
                          + (lane << 2) + wbyte;
    *p = (unsigned char)(*p + 1u);
}

__device__ __forceinline__ int bin_of(float x) {
    return min(max((int)(x * 256.0f), 0), NBINS - 1);
}

// Branchless per-pixel interpolate on the fixed fs grid + clip + rescale-back.
__device__ __forceinline__ float apply1(float x,
                                        const float* __restrict__ fsv,
                                        const float* __restrict__ As,
                                        const float* __restrict__ Bs,
                                        float pm0, float pm255,
                                        float fs0, float fs255) {
    int j = (int)(x * 255.0f) + 1;
    j = min(max(j, 1), NBINS - 1);
    if (fsv[j - 1] > x) --j;
    j = max(j, 1);
    if (fsv[j] <= x) ++j;
    j = min(j, NBINS - 1);
    float r = fmaf(As[j], x, Bs[j]);
    if (x <= fs0)   r = pm0;
    if (x >= fs255) r = pm255;
    r = fminf(fmaxf(r, 0.0f), 1.0f);
    return fmaf(r, 255.0f / 127.0f, -1.0f);
}

__global__ void __launch_bounds__(TPB, 1) k_fused(const float* __restrict__ src,
                                                  const float* __restrict__ tgt,
                                                  float* __restrict__ out, int n) {
    __shared__ int   sh[2 * NBINS];
    __shared__ float fsv[NBINS], pmS[NBINS], As[NBINS], Bs[NBINS];
    __shared__ int   is_last;

    const int t    = threadIdx.x;
    const int lane = t & 31;
    const int wid  = t >> 5;
    const int wrow = wid >> 2;           // warpgroup row (0..NGROUPS-1)
    const int wbyte = wid & 3;           // byte-within-word owned by this warp
    const int nth  = gridDim.x * TPB;
    const int gtid = blockIdx.x * TPB + t;
    const int nq   = n >> 2;
    const float SC = 127.0f / 255.0f;

    unsigned char* hp = s_dyn;

    // zero the u8 counters (uint4 stores)
    {
        uint4* z = (uint4*)s_dyn;
        const int nz = HIST_BYTES / 16;
        for (int i = t; i < nz; i += TPB) z[i] = make_uint4(0, 0, 0, 0);
    }
    if (t < NBINS) {   // floating_space: np.arange semantics (f64 i*step -> f32)
        float v = (float)((double)t * (1.0 / 255.0));
        fsv[t] = fminf(fmaxf(v, 0.0f), 1.0f);
    }
    __syncthreads();

    const float4* s4 = (const float4*)src;
    const float4* t4 = (const float4*)tgt;
    float4*       o4 = (float4*)out;

    // ---------------- Phase 1: rescale + lane-private histograms ----------------
    float xr[4 * KQ];

    #pragma unroll
    for (int k = 0; k < KQ; ++k) {
        int q = gtid + k * nth;
        if (q < nq) {
            float4 a = s4[3 * q + 0];
            float4 b = s4[3 * q + 1];
            float4 c = s4[3 * q + 2];
            float x0 = (a.x + 1.0f) * SC, x1 = (a.w + 1.0f) * SC;
            float x2 = (b.z + 1.0f) * SC, x3 = (c.y + 1.0f) * SC;
            xr[4 * k + 0] = x0; xr[4 * k + 1] = x1;
            xr[4 * k + 2] = x2; xr[4 * k + 3] = x3;
            hinc(hp, 0, bin_of(x0), wrow, wbyte, lane);
            hinc(hp, 0, bin_of(x1), wrow, wbyte, lane);
            hinc(hp, 0, bin_of(x2), wrow, wbyte, lane);
            hinc(hp, 0, bin_of(x3), wrow, wbyte, lane);

            float4 ta = t4[3 * q + 0];
            float4 tb = t4[3 * q + 1];
            float4 tc = t4[3 * q + 2];
            float y0 = (ta.x + 1.0f) * SC * 0.299f + (ta.y + 1.0f) * SC * 0.587f + (ta.z + 1.0f) * SC * 0.114f;
            float y1 = (ta.w + 1.0f) * SC * 0.299f + (tb.x + 1.0f) * SC * 0.587f + (tb.y + 1.0f) * SC * 0.114f;
            float y2 = (tb.z + 1.0f) * SC * 0.299f + (tb.w + 1.0f) * SC * 0.587f + (tc.x + 1.0f) * SC * 0.114f;
            float y3 = (tc.y + 1.0f) * SC * 0.299f + (tc.z + 1.0f) * SC * 0.587f + (tc.w + 1.0f) * SC * 0.114f;
            hinc(hp, 1, bin_of(y0), wrow, wbyte, lane);
            hinc(hp, 1, bin_of(y1), wrow, wbyte, lane);
            hinc(hp, 1, bin_of(y2), wrow, wbyte, lane);
            hinc(hp, 1, bin_of(y3), wrow, wbyte, lane);
        }
    }
    // Overflow quads (only if n exceeds register capacity): spill x to out,
    // count via global atomics (slow path; unused at the benchmark shape).
    for (int q = gtid + KQ * nth; q < nq; q += nth) {
        float4 a = s4[3 * q + 0];
        float4 b = s4[3 * q + 1];
        float4 c = s4[3 * q + 2];
        float x0 = (a.x + 1.0f) * SC, x1 = (a.w + 1.0f) * SC;
        float x2 = (b.z + 1.0f) * SC, x3 = (c.y + 1.0f) * SC;
        o4[q] = make_float4(x0, x1, x2, x3);
        atomicAdd(&g_hist[bin_of(x0)], 1);
        atomicAdd(&g_hist[bin_of(x1)], 1);
        atomicAdd(&g_hist[bin_of(x2)], 1);
        atomicAdd(&g_hist[bin_of(x3)], 1);
        float4 ta = t4[3 * q + 0];
        float4 tb = t4[3 * q + 1];
        float4 tc = t4[3 * q + 2];
        float y0 = (ta.x + 1.0f) * SC * 0.299f + (ta.y + 1.0f) * SC * 0.587f + (ta.z + 1.0f) * SC * 0.114f;
        float y1 = (ta.w + 1.0f) * SC * 0.299f + (tb.x + 1.0f) * SC * 0.587f + (tb.y + 1.0f) * SC * 0.114f;
        float y2 = (tb.z + 1.0f) * SC * 0.299f + (tb.w + 1.0f) * SC * 0.587f + (tc.x + 1.0f) * SC * 0.114f;
        float y3 = (tc.y + 1.0f) * SC * 0.299f + (tc.z + 1.0f) * SC * 0.587f + (tc.w + 1.0f) * SC * 0.114f;
        atomicAdd(&g_hist[NBINS + bin_of(y0)], 1);
        atomicAdd(&g_hist[NBINS + bin_of(y1)], 1);
        atomicAdd(&g_hist[NBINS + bin_of(y2)], 1);
        atomicAdd(&g_hist[NBINS + bin_of(y3)], 1);
    }
    // Tail pixels (n % 4): at most 3, via global atomics, x kept in register.
    float xtail = 0.0f;
    const int tidx = 4 * nq + gtid;
    if (tidx < n) {
        xtail = (src[3 * tidx] + 1.0f) * SC;
        atomicAdd(&g_hist[bin_of(xtail)], 1);
        float yr = (tgt[3 * tidx + 0] + 1.0f) * SC;
        float yg = (tgt[3 * tidx + 1] + 1.0f) * SC;
        float yb = (tgt[3 * tidx + 2] + 1.0f) * SC;
        atomicAdd(&g_hist[NBINS + bin_of(yr * 0.299f + yg * 0.587f + yb * 0.114f)], 1);
    }
    __syncthreads();

    // ---------------- Block reduction of u8 counters -> global ints ----------------
    // (h,bin) pair p handled by thread p (and p+TPB if TPB<512): sum 256 bytes.
    for (int p = t; p < 2 * NBINS; p += TPB) {
        unsigned int sum = 0;
        #pragma unroll
        for (int g = 0; g < NGROUPS; ++g) {
            const uint4* row = (const uint4*)(hp + (((p * NGROUPS) + g) << 7));
            #pragma unroll
            for (int u = 0; u < 8; ++u) {
                uint4 v = row[u];
                sum = __dp4a(v.x, 0x01010101u, sum);
                sum = __dp4a(v.y, 0x01010101u, sum);
                sum = __dp4a(v.z, 0x01010101u, sum);
                sum = __dp4a(v.w, 0x01010101u, sum);
            }
        }
        if (sum) atomicAdd(&g_hist[p], (int)sum);
    }

    // ---------------- Device-wide barrier ----------------
    __syncthreads();
    if (t == 0) {
        __threadfence();
        int old = atomicAdd(&g_done0, 1);
        is_last = (old == (int)gridDim.x - 1);
    }
    __syncthreads();

    if (is_last) {
        // ---- CDF + pxmap (first 256 threads of this block) ----
        __threadfence();
        if (t < NBINS) {
            sh[t]         = *(volatile int*)&g_hist[t];
            sh[t + NBINS] = *(volatile int*)&g_hist[t + NBINS];
        }
        __syncthreads();
        #pragma unroll
        for (int off = 1; off < NBINS; off <<= 1) {
            int aself = 0, bself = 0, aprev = 0, bprev = 0;
            if (t < NBINS) {
                aself = sh[t]; bself = sh[t + NBINS];
                if (t >= off) { aprev = sh[t - off]; bprev = sh[t + NBINS - off]; }
            }
            __syncthreads();
            if (t < NBINS) { sh[t] = aself + aprev; sh[t + NBINS] = bself + bprev; }
            __syncthreads();
        }
        if (t < NBINS) {
            int mins = sh[0], mint = sh[NBINS];
            float den = (float)(n - 1);
            float x  = (float)(sh[t] - mins) / den;          // cdfsrc[t]
            As[t] = (float)(sh[t + NBINS] - mint) / den;     // temp: cdftgt[t]
        }
        __syncthreads();
        if (t < NBINS) {
            float x;
            {
                int mins = sh[0];
                x = (float)(sh[t] - mins) / (float)(n - 1);
            }
            // upper_bound on sorted cdftgt; edge cases overridden below
            int lo = 0, hi = NBINS - 1;
            while (lo < hi) { int mid = (lo + hi) >> 1; if (As[mid] > x) hi = mid; else lo = mid + 1; }
            int ind1 = lo;
            int ind0 = max(ind1 - 1, 0);
            float dx0 = As[ind0], dx1 = As[ind1];
            float dy0 = fsv[ind0], dy1 = fsv[ind1];
            float dnm = dx1 - dx0;
            float sd  = (dnm == 0.0f) ? 1.0f : dnm;
            float interp = dy0 + (dy1 - dy0) * (x - dx0) / sd;
            float res = (x <= As[0]) ? fsv[0]
                      : ((x >= As[NBINS - 1]) ? fsv[NBINS - 1] : interp);
            pmS[t] = res;
            g_pxmap[t] = res;
        }
        __threadfence();
        __syncthreads();
        if (t == 0) g_release = 1;
    } else {
        if (t == 0) {
            while (g_release == 0) __nanosleep(32);
            __threadfence();   // acquire
        }
        __syncthreads();
        if (t < NBINS) pmS[t] = __ldcg(&g_pxmap[t]);
    }
    __syncthreads();

    // ---- slope/intercept tables ----
    if (t > 0 && t < NBINS) {
        float d = fsv[t] - fsv[t - 1];          // strictly > 0
        float a = (pmS[t] - pmS[t - 1]) / d;
        As[t] = a;
        Bs[t] = pmS[t - 1] - a * fsv[t - 1];
    }
    __syncthreads();

    // ---------------- Phase 3: apply ----------------
    const float pm0 = pmS[0], pm255 = pmS[NBINS - 1];
    const float fs0 = fsv[0], fs255 = fsv[NBINS - 1];

    #pragma unroll
    for (int k = 0; k < KQ; ++k) {
        int q = gtid + k * nth;
        if (q < nq) {
            float4 v;
            v.x = apply1(xr[4 * k + 0], fsv, As, Bs, pm0, pm255, fs0, fs255);
            v.y = apply1(xr[4 * k + 1], fsv, As, Bs, pm0, pm255, fs0, fs255);
            v.z = apply1(xr[4 * k + 2], fsv, As, Bs, pm0, pm255, fs0, fs255);
            v.w = apply1(xr[4 * k + 3], fsv, As, Bs, pm0, pm255, fs0, fs255);
            o4[q] = v;
        }
    }
    for (int q = gtid + KQ * nth; q < nq; q += nth) {
        float4 v = o4[q];   // spilled x values
        v.x = apply1(v.x, fsv, As, Bs, pm0, pm255, fs0, fs255);
        v.y = apply1(v.y, fsv, As, Bs, pm0, pm255, fs0, fs255);
        v.z = apply1(v.z, fsv, As, Bs, pm0, pm255, fs0, fs255);
        v.w = apply1(v.w, fsv, As, Bs, pm0, pm255, fs0, fs255);
        o4[q] = v;
    }
    if (tidx < n) out[tidx] = apply1(xtail, fsv, As, Bs, pm0, pm255, fs0, fs255);

    // ---------------- Cleanup: restore globals for next replay ----------------
    __syncthreads();
    if (t == 0) {
        __threadfence();
        int old = atomicAdd(&g_done1, 1);
        if (old == (int)gridDim.x - 1) {
            #pragma unroll 8
            for (int i = 0; i < 2 * NBINS; ++i) g_hist[i] = 0;
            g_done0 = 0;
            g_done1 = 0;
            __threadfence();
            g_release = 0;
        }
    }
}

extern "C" void kernel_launch(void* const* d_in, const int* in_sizes, int n_in,
                              void* d_out, int out_size) {
    const float* src = (const float*)d_in[0];
    const float* tgt = (const float*)d_in[1];
    float* out = (float*)d_out;
    int n = in_sizes[0] / 3;   // H*W pixels

    cudaFuncSetAttribute(k_fused, cudaFuncAttributeMaxDynamicSharedMemorySize,
                         HIST_BYTES);

    int blocks = 148;   // 1 CTA/SM, all co-resident (192KB smem/CTA)
    k_fused<<<blocks, TPB, HIST_BYTES>>>(src, tgt, out, n);
}